// round 10
// baseline (speedup 1.0000x reference)
#include <cuda_runtime.h>
#include <stdint.h>

// ---------------- problem constants ----------------
#define BN 4
#define DD 81
#define KK 2048
#define ND 4

// ---------------- fused GEMM config (fp16 m16n8k16) ----------------
#define MPAD 96
#define NTILE 256
#define KCH 64
#define KSPLIT 4
#define KSEG (KK / KSPLIT)  // 512
#define NSTG (KSEG / KCH)   // 8
#define NSTRIDE 264         // u32 words per kpair row (mod 32 = 8 -> conflict-free)
#define ABYTES 12288
#define APB 13824           // A(12288) + muP(1024) + rinv(256) + pad
#define BBYTES (32 * NSTRIDE * 4)   // 33792
#define BBASE (3 * APB)             // 41472
#define DYN_SMEM (BBASE + 2 * BBYTES)  // 109056
#define NCTA 128

// ---------------- static device scratch ----------------
__device__ float    g_pp[(size_t)BN * KK * 12];        // {mu[4], sig2[4], w, pad[3]}
__device__ float    g_muP[(size_t)BN * 1024 * 8];      // paired mu: [b][kpair][dim] float2
__device__ float    g_rinv[BN * KK];
__device__ uint32_t g_Ah[(size_t)BN * 128 * 6 * 128];  // fp16 frag-packed A
__device__ float    g_part[(size_t)KSPLIT * BN * MPAD * KK];
__device__ int      g_cnt[3];
__device__ int      g_epoch[3];

// ---------------- helpers ----------------
typedef unsigned long long ull;
__device__ __forceinline__ float frcp(float v) {
    float r; asm("rcp.approx.ftz.f32 %0, %1;" : "=f"(r) : "f"(v)); return r;
}
__device__ __forceinline__ uint32_t f16x2(float lo, float hi) {
    uint32_t r; asm("cvt.rn.f16x2.f32 %0, %1, %2;" : "=r"(r) : "f"(hi), "f"(lo)); return r;
}
__device__ __forceinline__ ull pack2(float lo, float hi) {
    ull r; asm("mov.b64 %0, {%1, %2};" : "=l"(r) : "f"(lo), "f"(hi)); return r;
}
__device__ __forceinline__ ull splat2(float v) {
    ull r; asm("mov.b64 %0, {%1, %1};" : "=l"(r) : "f"(v)); return r;
}
__device__ __forceinline__ void unpack2(ull v, float& lo, float& hi) {
    asm("mov.b64 {%0, %1}, %2;" : "=f"(lo), "=f"(hi) : "l"(v));
}
__device__ __forceinline__ ull add2(ull a, ull b) {
    ull r; asm("add.rn.f32x2 %0, %1, %2;" : "=l"(r) : "l"(a), "l"(b)); return r;
}
__device__ __forceinline__ ull mul2(ull a, ull b) {
    ull r; asm("mul.rn.f32x2 %0, %1, %2;" : "=l"(r) : "l"(a), "l"(b)); return r;
}
__device__ __forceinline__ ull fma2(ull a, ull b, ull c) {
    ull r; asm("fma.rn.f32x2 %0, %1, %2, %3;" : "=l"(r) : "l"(a), "l"(b), "l"(c)); return r;
}
__device__ __forceinline__ uint32_t smem_u32(const void* p) {
    uint32_t a;
    asm("{ .reg .u64 t; cvta.to.shared.u64 t, %1; cvt.u32.u64 %0, t; }" : "=r"(a) : "l"(p));
    return a;
}
__device__ __forceinline__ void cpasync16(uint32_t dst, const void* src) {
    asm volatile("cp.async.cg.shared.global [%0], [%1], 16;" :: "r"(dst), "l"(src));
}
#define CP_COMMIT() asm volatile("cp.async.commit_group;" ::: "memory")
#define CP_WAIT(n)  asm volatile("cp.async.wait_group %0;" :: "n"(n) : "memory")

__device__ __forceinline__ void mma_f16(float* d, const uint32_t* a, const uint32_t* b) {
    asm volatile(
        "mma.sync.aligned.m16n8k16.row.col.f32.f16.f16.f32 "
        "{%0,%1,%2,%3}, {%4,%5,%6,%7}, {%8,%9}, {%0,%1,%2,%3};"
        : "+f"(d[0]), "+f"(d[1]), "+f"(d[2]), "+f"(d[3])
        : "r"(a[0]), "r"(a[1]), "r"(a[2]), "r"(a[3]), "r"(b[0]), "r"(b[1]));
}

// Grid-wide barrier: monotonic epoch + count. Epoch read strictly before own
// arrival -> race-free; epoch never resets -> graph-replay safe; cnt resets
// before the release store of the new epoch.
__device__ __forceinline__ void grid_bar(int i) {
    __syncthreads();
    if (threadIdx.x == 0) {
        int* cp = &g_cnt[i];
        int* ep = &g_epoch[i];
        int e0;
        asm volatile("ld.acquire.gpu.s32 %0, [%1];" : "=r"(e0) : "l"(ep) : "memory");
        __threadfence();
        if (atomicAdd(cp, 1) == NCTA - 1) {
            *cp = 0;
            asm volatile("st.release.gpu.s32 [%0], %1;" :: "l"(ep), "r"(e0 + 1) : "memory");
        } else {
            int e;
            do {
                asm volatile("ld.acquire.gpu.s32 %0, [%1];" : "=r"(e) : "l"(ep) : "memory");
            } while (e == e0);
        }
    }
    __syncthreads();
}

// ================= single persistent kernel =================
__global__ __launch_bounds__(512, 1) void mono_kernel(
    const float* __restrict__ x, const float* __restrict__ pi,
    const float* __restrict__ mu, const float* __restrict__ sig,
    float* __restrict__ y) {
    extern __shared__ char dsm[];
    uint32_t sbase = smem_u32(dsm);
    int tid = threadIdx.x;
    int cta = blockIdx.z * 32 + blockIdx.y * 8 + blockIdx.x;

    // ================= P0: param pack + A fp16 frag-pack =================
    if (tid < 64) {
        int i = cta * 64 + tid;              // 0..8191 = (b,k)
        int b = i >> 11, k = i & 2047;
        float mv[4], sv[4], prod = 1.0f;
#pragma unroll
        for (int n = 0; n < ND; n++) {
            mv[n] = mu[(b * ND + n) * KK + k];
            float s = sig[(b * ND + n) * KK + k];
            sv[n] = s * s;
            prod *= s;
        }
        float* dst = g_pp + (size_t)i * 12;
        *(float4*)(dst + 0) = make_float4(mv[0], mv[1], mv[2], mv[3]);
        *(float4*)(dst + 4) = make_float4(sv[0], sv[1], sv[2], sv[3]);
        *(float4*)(dst + 8) = make_float4(pi[i] * prod, 0.0f, 0.0f, 0.0f);
        size_t pb = ((size_t)(b * 1024 + (k >> 1)) * 4) * 2 + (k & 1);
#pragma unroll
        for (int n = 0; n < ND; n++) g_muP[pb + n * 2] = mv[n];
    }
    // A-pack: 512 kb16-blocks x 192 lanes = 98304 items; 768 per CTA
    for (int k2 = tid; k2 < 768; k2 += 512) {
        int f = cta * 768 + k2;
        int kbg = f / 192, t = f - kbg * 192;
        int b = kbg >> 7, kb = kbg & 127;
        int mfg = t >> 5, lane = t & 31;
        int g = lane >> 2, c = lane & 3;
        int m0 = mfg * 16 + g, m1 = m0 + 8;
        int k0 = kb * 16 + 2 * c;
        const float* xb = x + (size_t)b * DD * KK;
        float2 z = make_float2(0.0f, 0.0f);
        float2 xa = (m0 < DD) ? *(const float2*)(xb + (size_t)m0 * KK + k0)     : z;
        float2 xb2 = (m0 < DD) ? *(const float2*)(xb + (size_t)m0 * KK + k0 + 8) : z;
        float2 xc = (m1 < DD) ? *(const float2*)(xb + (size_t)m1 * KK + k0)     : z;
        float2 xd = (m1 < DD) ? *(const float2*)(xb + (size_t)m1 * KK + k0 + 8) : z;
        uint4 out;
        out.x = f16x2(xa.x, xa.y);
        out.y = f16x2(xc.x, xc.y);
        out.z = f16x2(xb2.x, xb2.y);
        out.w = f16x2(xd.x, xd.y);
        *(uint4*)(g_Ah + (((size_t)kbg * 6 + mfg) * 128 + lane * 4)) = out;
    }
    grid_bar(0);

    // ================= P1: row sums (64 p-rows per CTA) =================
    {
        int b = cta >> 5, pblk = cta & 31;
        float* smu = (float*)dsm;            // 64 f
        float* red = (float*)dsm + 64;       // 16*17 f
        int lane = tid & 31, wid = tid >> 5;
#pragma unroll 1
        for (int sb = 0; sb < 4; sb++) {
            int p0 = pblk * 64 + sb * 16;
            if (tid < 64)
                smu[tid] = g_pp[(size_t)(b * KK + p0 + (tid >> 2)) * 12 + (tid & 3)];
            __syncthreads();

            ull muPP[8][4];
#pragma unroll
            for (int j = 0; j < 8; j++)
#pragma unroll
                for (int n = 0; n < 4; n++)
                    muPP[j][n] = pack2(smu[(2 * j) * 4 + n], smu[(2 * j + 1) * 4 + n]);

            float acc[16];
#pragma unroll
            for (int j = 0; j < 16; j++) acc[j] = 0.0f;

            for (int m = tid; m < KK; m += 512) {
                const float* c = g_pp + (size_t)(b * KK + m) * 12;
                float4 cm = *(const float4*)c;
                float4 cs = *(const float4*)(c + 4);
                float w = c[8];
                ull nm0 = splat2(-cm.x), nm1 = splat2(-cm.y), nm2 = splat2(-cm.z), nm3 = splat2(-cm.w);
                ull s0 = splat2(cs.x), s1 = splat2(cs.y), s2 = splat2(cs.z), s3 = splat2(cs.w);
#pragma unroll
                for (int j = 0; j < 8; j++) {
                    ull d0 = add2(muPP[j][0], nm0);
                    ull d1 = add2(muPP[j][1], nm1);
                    ull d2 = add2(muPP[j][2], nm2);
                    ull d3 = add2(muPP[j][3], nm3);
                    ull q = mul2(mul2(fma2(d0, d0, s0), fma2(d1, d1, s1)),
                                 mul2(fma2(d2, d2, s2), fma2(d3, d3, s3)));
                    float ql, qh; unpack2(q, ql, qh);
                    acc[2 * j]     = fmaf(w, frcp(ql), acc[2 * j]);
                    acc[2 * j + 1] = fmaf(w, frcp(qh), acc[2 * j + 1]);
                }
            }
            __syncthreads();   // smu no longer needed; red reuse safe
#pragma unroll
            for (int j = 0; j < 16; j++) {
                float v = acc[j];
#pragma unroll
                for (int o = 16; o > 0; o >>= 1) v += __shfl_xor_sync(0xffffffffu, v, o);
                if (lane == 0) red[wid * 17 + j] = v;
            }
            __syncthreads();
            if (tid < 16) {
                float s = 0.0f;
#pragma unroll
                for (int w = 0; w < 16; w++) s += red[w * 17 + tid];
                g_rinv[b * KK + p0 + tid] = 1.0f / s;
            }
            __syncthreads();
        }
    }
    grid_bar(1);

    // ================= P2: fused fp16 GEMM =================
    {
        int wid = tid >> 5, lane = tid & 31;
        int n0 = blockIdx.x * NTILE, ks = blockIdx.y, b = blockIdx.z;
        int kb0 = ks * (KSEG / 16);

        int ncol = tid & 255;
        int khalf = tid >> 8;
        ull snmu[4], s2v[4], sw;
        {
            const float* cp = g_pp + (size_t)(b * KK + n0 + ncol) * 12;
#pragma unroll
            for (int n = 0; n < 4; n++) {
                snmu[n] = splat2(-cp[n]);
                s2v[n]  = splat2(cp[4 + n]);
            }
            sw = splat2(cp[8]);
        }

        int warpM = wid >> 3, warpN = wid & 7;
        int nbase = warpN * 32;
        int g = lane >> 2, c = lane & 3;
        float acc[3][4][4];
#pragma unroll
        for (int i = 0; i < 3; i++)
#pragma unroll
            for (int j = 0; j < 4; j++)
#pragma unroll
                for (int q = 0; q < 4; q++) acc[i][j][q] = 0.0f;

        const uint4* gA = (const uint4*)(g_Ah + (size_t)b * 128 * 6 * 128);
        const float4* gMu = (const float4*)g_muP + (size_t)(b * 1024 + ks * 256) * 2;
        const float* gRi = g_rinv + b * KK + ks * KSEG;

        auto cp_stage = [&](int s) {
            uint32_t ab = sbase + (uint32_t)(s % 3) * APB;
            const uint4* srcA = gA + (size_t)(kb0 + s * 4) * 192;
            cpasync16(ab + (uint32_t)tid * 16u, srcA + tid);
            if (tid < 256) cpasync16(ab + (uint32_t)(tid + 512) * 16u, srcA + tid + 512);
            if (tid < 64) cpasync16(ab + 12288u + (uint32_t)tid * 16u, gMu + s * 64 + tid);
            if (tid < 16) cpasync16(ab + 13312u + (uint32_t)tid * 16u, gRi + s * 64 + tid * 4);
            CP_COMMIT();
        };

        auto gen_chunk = [&](int s, int kb) {
            uint32_t* Bs = (uint32_t*)(dsm + BBASE + (size_t)(s & 1) * BBYTES);
            const float* P = (const float*)(dsm + (size_t)(s % 3) * APB + 12288);
            const float* RI = (const float*)(dsm + (size_t)(s % 3) * APB + 13312);
#pragma unroll
            for (int i = 0; i < 4; i++) {
                int kp = kb * 8 + khalf * 4 + i;
                ull d0 = add2(*(const ull*)(P + kp * 8 + 0), snmu[0]);
                ull d1 = add2(*(const ull*)(P + kp * 8 + 2), snmu[1]);
                ull d2 = add2(*(const ull*)(P + kp * 8 + 4), snmu[2]);
                ull d3 = add2(*(const ull*)(P + kp * 8 + 6), snmu[3]);
                ull q = mul2(mul2(fma2(d0, d0, s2v[0]), fma2(d1, d1, s2v[1])),
                             mul2(fma2(d2, d2, s2v[2]), fma2(d3, d3, s2v[3])));
                float ql, qh; unpack2(q, ql, qh);
                ull wri = mul2(sw, *(const ull*)(RI + kp * 2));
                float wl, wh; unpack2(wri, wl, wh);
                float v0 = wl * frcp(ql);
                float v1 = wh * frcp(qh);
                Bs[kp * NSTRIDE + ncol] = f16x2(v0, v1);
            }
        };

        auto mma_kb = [&](int s, int kb) {
            const uint4* A4 = (const uint4*)(dsm + (size_t)(s % 3) * APB);
            const uint32_t* B = (const uint32_t*)(dsm + BBASE + (size_t)(s & 1) * BBYTES);
            uint32_t af[3][4], bf[4][2];
#pragma unroll
            for (int mf = 0; mf < 3; mf++) {
                uint4 av = A4[(kb * 6 + warpM * 3 + mf) * 32 + lane];
                af[mf][0] = av.x; af[mf][1] = av.y; af[mf][2] = av.z; af[mf][3] = av.w;
            }
            const uint32_t* Br0 = B + (kb * 8 + c) * NSTRIDE + nbase + g;
            const uint32_t* Br1 = B + (kb * 8 + c + 4) * NSTRIDE + nbase + g;
#pragma unroll
            for (int nf = 0; nf < 4; nf++) {
                bf[nf][0] = Br0[nf * 8];
                bf[nf][1] = Br1[nf * 8];
            }
#pragma unroll
            for (int mf = 0; mf < 3; mf++)
#pragma unroll
                for (int nf = 0; nf < 4; nf++)
                    mma_f16(acc[mf][nf], af[mf], bf[nf]);
        };

        cp_stage(0);
        cp_stage(1);
        CP_WAIT(1);
        __syncthreads();
#pragma unroll
        for (int kb = 0; kb < 4; kb++) gen_chunk(0, kb);
        __syncthreads();

        for (int s = 0; s < NSTG; s++) {
            if (s + 2 < NSTG) { cp_stage(s + 2); CP_WAIT(1); }
            else              { CP_WAIT(0); }
            if (s + 1 < NSTG) {
#pragma unroll
                for (int kb = 0; kb < 4; kb++) {
                    gen_chunk(s + 1, kb);
                    mma_kb(s, kb);
                }
            } else {
#pragma unroll
                for (int kb = 0; kb < 4; kb++) mma_kb(s, kb);
            }
            __syncthreads();
        }

        float* pp = g_part + ((size_t)(ks * BN + b) * MPAD) * KK + n0;
        int tig = lane & 3;
#pragma unroll
        for (int mf = 0; mf < 3; mf++) {
            int r0 = warpM * 48 + mf * 16 + g;
#pragma unroll
            for (int nf = 0; nf < 4; nf++) {
                int cc = nbase + nf * 8 + tig * 2;
                if (r0 < DD)
                    *(float2*)(pp + (size_t)r0 * KK + cc)       = make_float2(acc[mf][nf][0], acc[mf][nf][1]);
                if (r0 + 8 < DD)
                    *(float2*)(pp + (size_t)(r0 + 8) * KK + cc) = make_float2(acc[mf][nf][2], acc[mf][nf][3]);
            }
        }
    }
    grid_bar(2);

    // ================= P3: deterministic split-K reduce =================
    {
        const size_t slice = (size_t)BN * MPAD * KK / 4;
        const float4* p = (const float4*)g_part;
        int base = cta * 1296;
        for (int i = base + tid; i < base + 1296; i += 512) {
            int e = i * 4;
            int b = e / (DD * KK);
            int r = e - b * (DD * KK);
            int d = r / KK;
            int m = r - d * KK;
            size_t o = (((size_t)b * MPAD + d) * KK + m) / 4;
            float4 v0 = p[o], v1 = p[o + slice], v2 = p[o + 2 * slice], v3 = p[o + 3 * slice];
            ((float4*)y)[i] = make_float4(v0.x + v1.x + v2.x + v3.x,
                                          v0.y + v1.y + v2.y + v3.y,
                                          v0.z + v1.z + v2.z + v3.z,
                                          v0.w + v1.w + v2.w + v3.w);
        }
    }
}

// ---------------- launch ----------------
extern "C" void kernel_launch(void* const* d_in, const int* in_sizes, int n_in,
                              void* d_out, int out_size) {
    const float* x   = (const float*)d_in[0];  // (B, D, K)
    const float* pi  = (const float*)d_in[1];  // (B, 1, K)
    const float* mu  = (const float*)d_in[2];  // (B, ND, K)
    const float* sig = (const float*)d_in[3];  // (B, ND, K)
    float* y = (float*)d_out;                  // (B, D, K)

    cudaFuncSetAttribute(mono_kernel, cudaFuncAttributeMaxDynamicSharedMemorySize, DYN_SMEM);
    mono_kernel<<<dim3(8, 4, 4), 512, DYN_SMEM>>>(x, pi, mu, sig, y);
}

// round 12
// speedup vs baseline: 1.0450x; 1.0450x over previous
#include <cuda_runtime.h>
#include <stdint.h>

// ---------------- problem constants ----------------
#define BN 4
#define DD 81
#define KK 2048
#define ND 4

// ---------------- fused GEMM config (fp16 m16n8k16) ----------------
#define MPAD 96
#define NTILE 256
#define KCH 64
#define KSPLIT 4
#define KSEG (KK / KSPLIT)  // 512
#define NSTG (KSEG / KCH)   // 8
#define NSTRIDE 264         // u32 words per kpair row (mod 32 = 8 -> conflict-free)
#define ABYTES 12288        // fp16 frag-packed A stage
#define APB 13824           // A + mu4(1024) + rinv(256) + pad, triple buffered
#define BBYTES (32 * NSTRIDE * 4)   // 33792, double buffered
#define BBASE (3 * APB)             // 41472
#define DYN_SMEM (BBASE + 2 * BBYTES)  // 109056

// ---------------- static device scratch ----------------
__device__ float    g_pp[(size_t)BN * KK * 12];           // {mu[4], sig2[4], w, pad[3]}
__device__ float4   g_mu4[BN * KK];                       // compact mu rows
__device__ float    g_rinv[BN * KK];
__device__ uint32_t g_Ah[(size_t)BN * 128 * 6 * 128];     // fp16 frag-packed A (x only)
__device__ float    g_part[(size_t)KSPLIT * BN * MPAD * KK]; // split-K partials

// ---------------- helpers ----------------
typedef unsigned long long ull;
__device__ __forceinline__ float frcp(float v) {
    float r; asm("rcp.approx.ftz.f32 %0, %1;" : "=f"(r) : "f"(v)); return r;
}
__device__ __forceinline__ uint32_t f16x2(float lo, float hi) {
    uint32_t r; asm("cvt.rn.f16x2.f32 %0, %1, %2;" : "=r"(r) : "f"(hi), "f"(lo)); return r;
}
__device__ __forceinline__ ull pack2(float lo, float hi) {
    ull r; asm("mov.b64 %0, {%1, %2};" : "=l"(r) : "f"(lo), "f"(hi)); return r;
}
__device__ __forceinline__ ull splat2(float v) {
    ull r; asm("mov.b64 %0, {%1, %1};" : "=l"(r) : "f"(v)); return r;
}
__device__ __forceinline__ void unpack2(ull v, float& lo, float& hi) {
    asm("mov.b64 {%0, %1}, %2;" : "=f"(lo), "=f"(hi) : "l"(v));
}
__device__ __forceinline__ ull add2(ull a, ull b) {
    ull r; asm("add.rn.f32x2 %0, %1, %2;" : "=l"(r) : "l"(a), "l"(b)); return r;
}
__device__ __forceinline__ ull mul2(ull a, ull b) {
    ull r; asm("mul.rn.f32x2 %0, %1, %2;" : "=l"(r) : "l"(a), "l"(b)); return r;
}
__device__ __forceinline__ ull fma2(ull a, ull b, ull c) {
    ull r; asm("fma.rn.f32x2 %0, %1, %2, %3;" : "=l"(r) : "l"(a), "l"(b), "l"(c)); return r;
}
__device__ __forceinline__ uint32_t smem_u32(const void* p) {
    uint32_t a;
    asm("{ .reg .u64 t; cvta.to.shared.u64 t, %1; cvt.u32.u64 %0, t; }" : "=r"(a) : "l"(p));
    return a;
}
__device__ __forceinline__ void cpasync16(uint32_t dst, const void* src) {
    asm volatile("cp.async.cg.shared.global [%0], [%1], 16;" :: "r"(dst), "l"(src));
}
#define CP_COMMIT() asm volatile("cp.async.commit_group;" ::: "memory")
#define CP_WAIT(n)  asm volatile("cp.async.wait_group %0;" :: "n"(n) : "memory")

__device__ __forceinline__ void mma_f16(float* d, const uint32_t* a, const uint32_t* b) {
    asm volatile(
        "mma.sync.aligned.m16n8k16.row.col.f32.f16.f16.f32 "
        "{%0,%1,%2,%3}, {%4,%5,%6,%7}, {%8,%9}, {%0,%1,%2,%3};"
        : "+f"(d[0]), "+f"(d[1]), "+f"(d[2]), "+f"(d[3])
        : "r"(a[0]), "r"(a[1]), "r"(a[2]), "r"(a[3]), "r"(b[0]), "r"(b[1]));
}

// ---------------- K1: combined param-pack + A fp16 frag-pack ----------------
// grid (128, BN), 256 threads. t<192: A-pack lane for kb16=blockIdx.x.
// t in [192,208): param pack for k = blockIdx.x*16 + (t-192).
__global__ void prep_kernel(const float* __restrict__ x,
                            const float* __restrict__ pi,
                            const float* __restrict__ mu,
                            const float* __restrict__ sig) {
    int kb = blockIdx.x, b = blockIdx.y;
    int t = threadIdx.x;
    if (t < 192) {
        int mfg = t >> 5, lane = t & 31;
        int g = lane >> 2, c = lane & 3;
        int m0 = mfg * 16 + g, m1 = m0 + 8;
        int k0 = kb * 16 + 2 * c;
        const float* xb = x + (size_t)b * DD * KK;
        float2 z = make_float2(0.0f, 0.0f);
        float2 xa = (m0 < DD) ? *(const float2*)(xb + (size_t)m0 * KK + k0)     : z;
        float2 xb2 = (m0 < DD) ? *(const float2*)(xb + (size_t)m0 * KK + k0 + 8) : z;
        float2 xc = (m1 < DD) ? *(const float2*)(xb + (size_t)m1 * KK + k0)     : z;
        float2 xd = (m1 < DD) ? *(const float2*)(xb + (size_t)m1 * KK + k0 + 8) : z;
        uint4 out;
        out.x = f16x2(xa.x, xa.y);
        out.y = f16x2(xc.x, xc.y);
        out.z = f16x2(xb2.x, xb2.y);
        out.w = f16x2(xd.x, xd.y);
        *(uint4*)(g_Ah + (((size_t)(b * 128 + kb) * 6 + mfg) * 128 + lane * 4)) = out;
    } else if (t < 208) {
        int k = kb * 16 + (t - 192);
        int i = b * KK + k;
        float mv[4], sv[4], prod = 1.0f;
#pragma unroll
        for (int n = 0; n < ND; n++) {
            mv[n] = mu[(b * ND + n) * KK + k];
            float s = sig[(b * ND + n) * KK + k];
            sv[n] = s * s;
            prod *= s;
        }
        float* dst = g_pp + (size_t)i * 12;
        *(float4*)(dst + 0) = make_float4(mv[0], mv[1], mv[2], mv[3]);
        *(float4*)(dst + 4) = make_float4(sv[0], sv[1], sv[2], sv[3]);
        *(float4*)(dst + 8) = make_float4(pi[i] * prod, 0.0f, 0.0f, 0.0f);
        g_mu4[i] = make_float4(mv[0], mv[1], mv[2], mv[3]);
    }
}

// ---------------- K2: row sums, 2 sequential 16-row groups (L1 reuse) ----------------
// grid (64, BN) = 256 blocks, 256 threads. Group 2's g_pp reads hit L1.
__global__ __launch_bounds__(256) void rowsum_kernel() {
    int b = blockIdx.y;
    int tid = threadIdx.x;
    int lane = tid & 31, wid = tid >> 5;

    __shared__ float smu[16][4];
    __shared__ float red[8][17];

#pragma unroll 1
    for (int grp = 0; grp < 2; grp++) {
        int p0 = (blockIdx.x * 2 + grp) * 16;
        if (tid < 16) {
            float4 v = g_mu4[b * KK + p0 + tid];
            smu[tid][0] = v.x; smu[tid][1] = v.y; smu[tid][2] = v.z; smu[tid][3] = v.w;
        }
        __syncthreads();

        ull muPP[8][4];
#pragma unroll
        for (int j = 0; j < 8; j++)
#pragma unroll
            for (int n = 0; n < 4; n++) muPP[j][n] = pack2(smu[2 * j][n], smu[2 * j + 1][n]);

        float acc[16];
#pragma unroll
        for (int j = 0; j < 16; j++) acc[j] = 0.0f;

        for (int m = tid; m < KK; m += 256) {
            const float* c = g_pp + (size_t)(b * KK + m) * 12;
            float4 cm = *(const float4*)c;
            float4 cs = *(const float4*)(c + 4);
            float w = c[8];
            ull nm0 = splat2(-cm.x), nm1 = splat2(-cm.y), nm2 = splat2(-cm.z), nm3 = splat2(-cm.w);
            ull s0 = splat2(cs.x), s1 = splat2(cs.y), s2 = splat2(cs.z), s3 = splat2(cs.w);
#pragma unroll
            for (int j = 0; j < 8; j++) {
                ull d0 = add2(muPP[j][0], nm0);
                ull d1 = add2(muPP[j][1], nm1);
                ull d2 = add2(muPP[j][2], nm2);
                ull d3 = add2(muPP[j][3], nm3);
                ull q = mul2(mul2(fma2(d0, d0, s0), fma2(d1, d1, s1)),
                             mul2(fma2(d2, d2, s2), fma2(d3, d3, s3)));
                float ql, qh; unpack2(q, ql, qh);
                acc[2 * j]     = fmaf(w, frcp(ql), acc[2 * j]);
                acc[2 * j + 1] = fmaf(w, frcp(qh), acc[2 * j + 1]);
            }
        }

        __syncthreads();
#pragma unroll
        for (int j = 0; j < 16; j++) {
            float v = acc[j];
#pragma unroll
            for (int o = 16; o > 0; o >>= 1) v += __shfl_xor_sync(0xffffffffu, v, o);
            if (lane == 0) red[wid][j] = v;
        }
        __syncthreads();
        if (tid < 16) {
            float s = 0.0f;
#pragma unroll
            for (int w = 0; w < 8; w++) s += red[w][tid];
            g_rinv[b * KK + p0 + tid] = 1.0f / s;
        }
        __syncthreads();
    }
}

// ---------------- K3: fused fp16 GEMM (unchanged from R9) ----------------
// grid (KK/NTILE=8, KSPLIT=4, BN=4) = 128 CTAs, 512 threads (16 warps = 2M x 8N).
__global__ __launch_bounds__(512, 1) void gemm_fused() {
    extern __shared__ char dsm[];
    uint32_t sbase = smem_u32(dsm);

    int tid = threadIdx.x, wid = tid >> 5, lane = tid & 31;
    int n0 = blockIdx.x * NTILE, ks = blockIdx.y, b = blockIdx.z;
    int kb0 = ks * (KSEG / 16);

    int ncol = tid & 255;
    int khalf = tid >> 8;
    ull snmu[4], s2v[4];
    float w_m;
    {
        const float* cp = g_pp + (size_t)(b * KK + n0 + ncol) * 12;
#pragma unroll
        for (int n = 0; n < 4; n++) {
            snmu[n] = splat2(-cp[n]);
            s2v[n]  = splat2(cp[4 + n]);
        }
        w_m = cp[8];
    }

    int warpM = wid >> 3, warpN = wid & 7;
    int nbase = warpN * 32;
    int g = lane >> 2, c = lane & 3;
    float acc[3][4][4];
#pragma unroll
    for (int i = 0; i < 3; i++)
#pragma unroll
        for (int j = 0; j < 4; j++)
#pragma unroll
            for (int q = 0; q < 4; q++) acc[i][j][q] = 0.0f;

    const uint4* gA = (const uint4*)(g_Ah + (size_t)b * 128 * 6 * 128);
    const float4* gP = &g_mu4[b * KK + ks * KSEG];
    const float* gRi = g_rinv + b * KK + ks * KSEG;

    auto cp_stage = [&](int s) {
        uint32_t ab = sbase + (uint32_t)(s % 3) * APB;
        const uint4* srcA = gA + (size_t)(kb0 + s * 4) * 192;
        cpasync16(ab + (uint32_t)tid * 16u, srcA + tid);
        if (tid < 256) cpasync16(ab + (uint32_t)(tid + 512) * 16u, srcA + tid + 512);
        if (tid < 64) cpasync16(ab + 12288u + (uint32_t)tid * 16u, gP + s * 64 + tid);
        if (tid < 16) cpasync16(ab + 13312u + (uint32_t)tid * 16u, gRi + s * 64 + tid * 4);
        CP_COMMIT();
    };

    auto gen_chunk = [&](int s, int kb) {
        uint32_t* Bs = (uint32_t*)(dsm + BBASE + (size_t)(s & 1) * BBYTES);
        const float* P = (const float*)(dsm + (size_t)(s % 3) * APB + 12288);
        const float* RI = (const float*)(dsm + (size_t)(s % 3) * APB + 13312);
#pragma unroll
        for (int i = 0; i < 4; i++) {
            int kp = kb * 8 + khalf * 4 + i;
            int p2 = kp * 2;
            float4 mp0 = *(const float4*)(P + p2 * 4);
            float4 mp1 = *(const float4*)(P + p2 * 4 + 4);
            float2 ri = *(const float2*)(RI + p2);
            ull d0 = add2(pack2(mp0.x, mp1.x), snmu[0]);
            ull d1 = add2(pack2(mp0.y, mp1.y), snmu[1]);
            ull d2 = add2(pack2(mp0.z, mp1.z), snmu[2]);
            ull d3 = add2(pack2(mp0.w, mp1.w), snmu[3]);
            ull q = mul2(mul2(fma2(d0, d0, s2v[0]), fma2(d1, d1, s2v[1])),
                         mul2(fma2(d2, d2, s2v[2]), fma2(d3, d3, s2v[3])));
            float ql, qh; unpack2(q, ql, qh);
            float v0 = w_m * ri.x * frcp(ql);
            float v1 = w_m * ri.y * frcp(qh);
            Bs[kp * NSTRIDE + ncol] = f16x2(v0, v1);
        }
    };

    auto mma_kb = [&](int s, int kb) {
        const uint4* A4 = (const uint4*)(dsm + (size_t)(s % 3) * APB);
        const uint32_t* B = (const uint32_t*)(dsm + BBASE + (size_t)(s & 1) * BBYTES);
        uint32_t af[3][4], bf[4][2];
#pragma unroll
        for (int mf = 0; mf < 3; mf++) {
            uint4 av = A4[(kb * 6 + warpM * 3 + mf) * 32 + lane];
            af[mf][0] = av.x; af[mf][1] = av.y; af[mf][2] = av.z; af[mf][3] = av.w;
        }
        const uint32_t* Br0 = B + (kb * 8 + c) * NSTRIDE + nbase + g;
        const uint32_t* Br1 = B + (kb * 8 + c + 4) * NSTRIDE + nbase + g;
#pragma unroll
        for (int nf = 0; nf < 4; nf++) {
            bf[nf][0] = Br0[nf * 8];
            bf[nf][1] = Br1[nf * 8];
        }
#pragma unroll
        for (int mf = 0; mf < 3; mf++)
#pragma unroll
            for (int nf = 0; nf < 4; nf++)
                mma_f16(acc[mf][nf], af[mf], bf[nf]);
    };

    cp_stage(0);
    cp_stage(1);
    CP_WAIT(1);
    __syncthreads();
#pragma unroll
    for (int kb = 0; kb < 4; kb++) gen_chunk(0, kb);
    __syncthreads();

    for (int s = 0; s < NSTG; s++) {
        if (s + 2 < NSTG) { cp_stage(s + 2); CP_WAIT(1); }
        else              { CP_WAIT(0); }
        if (s + 1 < NSTG) {
#pragma unroll
            for (int kb = 0; kb < 4; kb++) {
                gen_chunk(s + 1, kb);
                mma_kb(s, kb);
            }
        } else {
#pragma unroll
            for (int kb = 0; kb < 4; kb++) mma_kb(s, kb);
        }
        __syncthreads();
    }

    float* pp = g_part + ((size_t)(ks * BN + b) * MPAD) * KK + n0;
    int tig = lane & 3;
#pragma unroll
    for (int mf = 0; mf < 3; mf++) {
        int r0 = warpM * 48 + mf * 16 + g;
#pragma unroll
        for (int nf = 0; nf < 4; nf++) {
            int cc = nbase + nf * 8 + tig * 2;
            if (r0 < DD)
                *(float2*)(pp + (size_t)r0 * KK + cc)       = make_float2(acc[mf][nf][0], acc[mf][nf][1]);
            if (r0 + 8 < DD)
                *(float2*)(pp + (size_t)(r0 + 8) * KK + cc) = make_float2(acc[mf][nf][2], acc[mf][nf][3]);
        }
    }
}

// ---------------- K4: deterministic split-K reduce (float4) ----------------
__global__ void reduce_kernel(float* __restrict__ y) {
    int i = blockIdx.x * 256 + threadIdx.x;   // float4 index
    const int total = BN * DD * KK / 4;
    if (i >= total) return;
    int e = i * 4;
    int b = e / (DD * KK);
    int r = e - b * (DD * KK);
    int d = r / KK;
    int m = r - d * KK;
    size_t o = (((size_t)b * MPAD + d) * KK + m) / 4;
    const size_t slice = (size_t)BN * MPAD * KK / 4;
    const float4* p = (const float4*)g_part;
    float4 v0 = p[o], v1 = p[o + slice], v2 = p[o + 2 * slice], v3 = p[o + 3 * slice];
    ((float4*)y)[i] = make_float4(v0.x + v1.x + v2.x + v3.x,
                                  v0.y + v1.y + v2.y + v3.y,
                                  v0.z + v1.z + v2.z + v3.z,
                                  v0.w + v1.w + v2.w + v3.w);
}

// ---------------- launch ----------------
extern "C" void kernel_launch(void* const* d_in, const int* in_sizes, int n_in,
                              void* d_out, int out_size) {
    const float* x   = (const float*)d_in[0];  // (B, D, K)
    const float* pi  = (const float*)d_in[1];  // (B, 1, K)
    const float* mu  = (const float*)d_in[2];  // (B, ND, K)
    const float* sig = (const float*)d_in[3];  // (B, ND, K)
    float* y = (float*)d_out;                  // (B, D, K)

    cudaFuncSetAttribute(gemm_fused, cudaFuncAttributeMaxDynamicSharedMemorySize, DYN_SMEM);

    prep_kernel<<<dim3(128, BN), 256>>>(x, pi, mu, sig);
    rowsum_kernel<<<dim3(64, BN), 256>>>();
    gemm_fused<<<dim3(KK / NTILE, KSPLIT, BN), 512, DYN_SMEM>>>();
    reduce_kernel<<<(BN * DD * KK / 4 + 255) / 256, 256>>>(y);
}

// round 13
// speedup vs baseline: 1.0606x; 1.0150x over previous
#include <cuda_runtime.h>
#include <stdint.h>

// ---------------- problem constants ----------------
#define BN 4
#define DD 81
#define KK 2048
#define ND 4

// ---------------- fused GEMM config (fp16 m16n8k16) ----------------
#define MPAD 96
#define NTILE 256
#define KCH 64
#define KSPLIT 4
#define KSEG (KK / KSPLIT)  // 512
#define NSTG (KSEG / KCH)   // 8
#define NSTRIDE 264         // u32 words per kpair row (mod 32 = 8 -> conflict-free)
#define ABYTES 12288        // fp16 frag-packed A stage
#define APB 13824           // A + mu4(1024) + rinv(256) + pad, triple buffered
#define BBYTES (32 * NSTRIDE * 4)   // 33792, double buffered
#define BBASE (3 * APB)             // 41472
#define DYN_SMEM (BBASE + 2 * BBYTES)  // 109056

// ---------------- static device scratch ----------------
__device__ float    g_pp[(size_t)BN * KK * 12];           // {mu[4], sig2[4], w, pad[3]}
__device__ float4   g_mu4[BN * KK];                       // compact mu rows
__device__ float    g_rinv[BN * KK];
__device__ uint32_t g_Ah[(size_t)BN * 128 * 6 * 128];     // fp16 frag-packed A (x only)
__device__ float    g_part[(size_t)KSPLIT * BN * MPAD * KK]; // split-K partials
__device__ int      g_sync[32];                           // per-(b,ntile) completion counters

// ---------------- helpers ----------------
typedef unsigned long long ull;
__device__ __forceinline__ float frcp(float v) {
    float r; asm("rcp.approx.ftz.f32 %0, %1;" : "=f"(r) : "f"(v)); return r;
}
__device__ __forceinline__ uint32_t f16x2(float lo, float hi) {
    uint32_t r; asm("cvt.rn.f16x2.f32 %0, %1, %2;" : "=r"(r) : "f"(hi), "f"(lo)); return r;
}
__device__ __forceinline__ ull pack2(float lo, float hi) {
    ull r; asm("mov.b64 %0, {%1, %2};" : "=l"(r) : "f"(lo), "f"(hi)); return r;
}
__device__ __forceinline__ ull splat2(float v) {
    ull r; asm("mov.b64 %0, {%1, %1};" : "=l"(r) : "f"(v)); return r;
}
__device__ __forceinline__ void unpack2(ull v, float& lo, float& hi) {
    asm("mov.b64 {%0, %1}, %2;" : "=f"(lo), "=f"(hi) : "l"(v));
}
__device__ __forceinline__ ull add2(ull a, ull b) {
    ull r; asm("add.rn.f32x2 %0, %1, %2;" : "=l"(r) : "l"(a), "l"(b)); return r;
}
__device__ __forceinline__ ull mul2(ull a, ull b) {
    ull r; asm("mul.rn.f32x2 %0, %1, %2;" : "=l"(r) : "l"(a), "l"(b)); return r;
}
__device__ __forceinline__ ull fma2(ull a, ull b, ull c) {
    ull r; asm("fma.rn.f32x2 %0, %1, %2, %3;" : "=l"(r) : "l"(a), "l"(b), "l"(c)); return r;
}
__device__ __forceinline__ uint32_t smem_u32(const void* p) {
    uint32_t a;
    asm("{ .reg .u64 t; cvta.to.shared.u64 t, %1; cvt.u32.u64 %0, t; }" : "=r"(a) : "l"(p));
    return a;
}
__device__ __forceinline__ void cpasync16(uint32_t dst, const void* src) {
    asm volatile("cp.async.cg.shared.global [%0], [%1], 16;" :: "r"(dst), "l"(src));
}
#define CP_COMMIT() asm volatile("cp.async.commit_group;" ::: "memory")
#define CP_WAIT(n)  asm volatile("cp.async.wait_group %0;" :: "n"(n) : "memory")

__device__ __forceinline__ void mma_f16(float* d, const uint32_t* a, const uint32_t* b) {
    asm volatile(
        "mma.sync.aligned.m16n8k16.row.col.f32.f16.f16.f32 "
        "{%0,%1,%2,%3}, {%4,%5,%6,%7}, {%8,%9}, {%0,%1,%2,%3};"
        : "+f"(d[0]), "+f"(d[1]), "+f"(d[2]), "+f"(d[3])
        : "r"(a[0]), "r"(a[1]), "r"(a[2]), "r"(a[3]), "r"(b[0]), "r"(b[1]));
}

// ---------------- K1: combined param-pack + A fp16 frag-pack + sync reset ----------------
// grid (128, BN), 256 threads.
__global__ void prep_kernel(const float* __restrict__ x,
                            const float* __restrict__ pi,
                            const float* __restrict__ mu,
                            const float* __restrict__ sig) {
    int kb = blockIdx.x, b = blockIdx.y;
    int t = threadIdx.x;
    if (t < 192) {
        int mfg = t >> 5, lane = t & 31;
        int g = lane >> 2, c = lane & 3;
        int m0 = mfg * 16 + g, m1 = m0 + 8;
        int k0 = kb * 16 + 2 * c;
        const float* xb = x + (size_t)b * DD * KK;
        float2 z = make_float2(0.0f, 0.0f);
        float2 xa = (m0 < DD) ? *(const float2*)(xb + (size_t)m0 * KK + k0)     : z;
        float2 xb2 = (m0 < DD) ? *(const float2*)(xb + (size_t)m0 * KK + k0 + 8) : z;
        float2 xc = (m1 < DD) ? *(const float2*)(xb + (size_t)m1 * KK + k0)     : z;
        float2 xd = (m1 < DD) ? *(const float2*)(xb + (size_t)m1 * KK + k0 + 8) : z;
        uint4 out;
        out.x = f16x2(xa.x, xa.y);
        out.y = f16x2(xc.x, xc.y);
        out.z = f16x2(xb2.x, xb2.y);
        out.w = f16x2(xd.x, xd.y);
        *(uint4*)(g_Ah + (((size_t)(b * 128 + kb) * 6 + mfg) * 128 + lane * 4)) = out;
    } else if (t < 208) {
        int k = kb * 16 + (t - 192);
        int i = b * KK + k;
        float mv[4], sv[4], prod = 1.0f;
#pragma unroll
        for (int n = 0; n < ND; n++) {
            mv[n] = mu[(b * ND + n) * KK + k];
            float s = sig[(b * ND + n) * KK + k];
            sv[n] = s * s;
            prod *= s;
        }
        float* dst = g_pp + (size_t)i * 12;
        *(float4*)(dst + 0) = make_float4(mv[0], mv[1], mv[2], mv[3]);
        *(float4*)(dst + 4) = make_float4(sv[0], sv[1], sv[2], sv[3]);
        *(float4*)(dst + 8) = make_float4(pi[i] * prod, 0.0f, 0.0f, 0.0f);
        g_mu4[i] = make_float4(mv[0], mv[1], mv[2], mv[3]);
    } else if (t < 240 && kb == 0 && b == 0) {
        g_sync[t - 208] = 0;    // reset split-K completion counters each call
    }
}

// ---------------- K2: row sums (R9 shape: 512 blocks, 16 p rows each) ----------------
__global__ __launch_bounds__(256) void rowsum_kernel() {
    int b = blockIdx.y;
    int p0 = blockIdx.x * 16;
    int tid = threadIdx.x;

    __shared__ float smu[16][4];
    if (tid < 16) {
        float4 v = g_mu4[b * KK + p0 + tid];
        smu[tid][0] = v.x; smu[tid][1] = v.y; smu[tid][2] = v.z; smu[tid][3] = v.w;
    }
    __syncthreads();

    ull muPP[8][4];
#pragma unroll
    for (int j = 0; j < 8; j++)
#pragma unroll
        for (int n = 0; n < 4; n++) muPP[j][n] = pack2(smu[2 * j][n], smu[2 * j + 1][n]);

    float acc[16];
#pragma unroll
    for (int j = 0; j < 16; j++) acc[j] = 0.0f;

    for (int m = tid; m < KK; m += 256) {
        const float* c = g_pp + (size_t)(b * KK + m) * 12;
        float4 cm = *(const float4*)c;
        float4 cs = *(const float4*)(c + 4);
        float w = c[8];
        ull nm0 = splat2(-cm.x), nm1 = splat2(-cm.y), nm2 = splat2(-cm.z), nm3 = splat2(-cm.w);
        ull s0 = splat2(cs.x), s1 = splat2(cs.y), s2 = splat2(cs.z), s3 = splat2(cs.w);
#pragma unroll
        for (int j = 0; j < 8; j++) {
            ull d0 = add2(muPP[j][0], nm0);
            ull d1 = add2(muPP[j][1], nm1);
            ull d2 = add2(muPP[j][2], nm2);
            ull d3 = add2(muPP[j][3], nm3);
            ull q = mul2(mul2(fma2(d0, d0, s0), fma2(d1, d1, s1)),
                         mul2(fma2(d2, d2, s2), fma2(d3, d3, s3)));
            float ql, qh; unpack2(q, ql, qh);
            acc[2 * j]     = fmaf(w, frcp(ql), acc[2 * j]);
            acc[2 * j + 1] = fmaf(w, frcp(qh), acc[2 * j + 1]);
        }
    }

    __shared__ float red[8][17];
    int lane = tid & 31, wid = tid >> 5;
#pragma unroll
    for (int j = 0; j < 16; j++) {
        float v = acc[j];
#pragma unroll
        for (int o = 16; o > 0; o >>= 1) v += __shfl_xor_sync(0xffffffffu, v, o);
        if (lane == 0) red[wid][j] = v;
    }
    __syncthreads();
    if (tid < 16) {
        float s = 0.0f;
#pragma unroll
        for (int w = 0; w < 8; w++) s += red[w][tid];
        g_rinv[b * KK + p0 + tid] = 1.0f / s;
    }
}

// ---------------- K3: fused fp16 GEMM + last-CTA split-K reduce ----------------
// grid (KK/NTILE=8, KSPLIT=4, BN=4) = 128 CTAs, 512 threads (16 warps = 2M x 8N).
__global__ __launch_bounds__(512, 1) void gemm_fused(float* __restrict__ y) {
    extern __shared__ char dsm[];
    uint32_t sbase = smem_u32(dsm);

    int tid = threadIdx.x, wid = tid >> 5, lane = tid & 31;
    int n0 = blockIdx.x * NTILE, ks = blockIdx.y, b = blockIdx.z;
    int kb0 = ks * (KSEG / 16);

    int ncol = tid & 255;
    int khalf = tid >> 8;
    ull snmu[4], s2v[4];
    float w_m;
    {
        const float* cp = g_pp + (size_t)(b * KK + n0 + ncol) * 12;
#pragma unroll
        for (int n = 0; n < 4; n++) {
            snmu[n] = splat2(-cp[n]);
            s2v[n]  = splat2(cp[4 + n]);
        }
        w_m = cp[8];
    }

    int warpM = wid >> 3, warpN = wid & 7;
    int nbase = warpN * 32;
    int g = lane >> 2, c = lane & 3;
    float acc[3][4][4];
#pragma unroll
    for (int i = 0; i < 3; i++)
#pragma unroll
        for (int j = 0; j < 4; j++)
#pragma unroll
            for (int q = 0; q < 4; q++) acc[i][j][q] = 0.0f;

    const uint4* gA = (const uint4*)(g_Ah + (size_t)b * 128 * 6 * 128);
    const float4* gP = &g_mu4[b * KK + ks * KSEG];
    const float* gRi = g_rinv + b * KK + ks * KSEG;

    auto cp_stage = [&](int s) {
        uint32_t ab = sbase + (uint32_t)(s % 3) * APB;
        const uint4* srcA = gA + (size_t)(kb0 + s * 4) * 192;
        cpasync16(ab + (uint32_t)tid * 16u, srcA + tid);
        if (tid < 256) cpasync16(ab + (uint32_t)(tid + 512) * 16u, srcA + tid + 512);
        if (tid < 64) cpasync16(ab + 12288u + (uint32_t)tid * 16u, gP + s * 64 + tid);
        if (tid < 16) cpasync16(ab + 13312u + (uint32_t)tid * 16u, gRi + s * 64 + tid * 4);
        CP_COMMIT();
    };

    auto gen_chunk = [&](int s, int kb) {
        uint32_t* Bs = (uint32_t*)(dsm + BBASE + (size_t)(s & 1) * BBYTES);
        const float* P = (const float*)(dsm + (size_t)(s % 3) * APB + 12288);
        const float* RI = (const float*)(dsm + (size_t)(s % 3) * APB + 13312);
#pragma unroll
        for (int i = 0; i < 4; i++) {
            int kp = kb * 8 + khalf * 4 + i;
            int p2 = kp * 2;
            float4 mp0 = *(const float4*)(P + p2 * 4);
            float4 mp1 = *(const float4*)(P + p2 * 4 + 4);
            float2 ri = *(const float2*)(RI + p2);
            ull d0 = add2(pack2(mp0.x, mp1.x), snmu[0]);
            ull d1 = add2(pack2(mp0.y, mp1.y), snmu[1]);
            ull d2 = add2(pack2(mp0.z, mp1.z), snmu[2]);
            ull d3 = add2(pack2(mp0.w, mp1.w), snmu[3]);
            ull q = mul2(mul2(fma2(d0, d0, s2v[0]), fma2(d1, d1, s2v[1])),
                         mul2(fma2(d2, d2, s2v[2]), fma2(d3, d3, s2v[3])));
            float ql, qh; unpack2(q, ql, qh);
            float v0 = w_m * ri.x * frcp(ql);
            float v1 = w_m * ri.y * frcp(qh);
            Bs[kp * NSTRIDE + ncol] = f16x2(v0, v1);
        }
    };

    auto mma_kb = [&](int s, int kb) {
        const uint4* A4 = (const uint4*)(dsm + (size_t)(s % 3) * APB);
        const uint32_t* B = (const uint32_t*)(dsm + BBASE + (size_t)(s & 1) * BBYTES);
        uint32_t af[3][4], bf[4][2];
#pragma unroll
        for (int mf = 0; mf < 3; mf++) {
            uint4 av = A4[(kb * 6 + warpM * 3 + mf) * 32 + lane];
            af[mf][0] = av.x; af[mf][1] = av.y; af[mf][2] = av.z; af[mf][3] = av.w;
        }
        const uint32_t* Br0 = B + (kb * 8 + c) * NSTRIDE + nbase + g;
        const uint32_t* Br1 = B + (kb * 8 + c + 4) * NSTRIDE + nbase + g;
#pragma unroll
        for (int nf = 0; nf < 4; nf++) {
            bf[nf][0] = Br0[nf * 8];
            bf[nf][1] = Br1[nf * 8];
        }
#pragma unroll
        for (int mf = 0; mf < 3; mf++)
#pragma unroll
            for (int nf = 0; nf < 4; nf++)
                mma_f16(acc[mf][nf], af[mf], bf[nf]);
    };

    cp_stage(0);
    cp_stage(1);
    CP_WAIT(1);
    __syncthreads();
#pragma unroll
    for (int kb = 0; kb < 4; kb++) gen_chunk(0, kb);
    __syncthreads();

    for (int s = 0; s < NSTG; s++) {
        if (s + 2 < NSTG) { cp_stage(s + 2); CP_WAIT(1); }
        else              { CP_WAIT(0); }
        if (s + 1 < NSTG) {
#pragma unroll
            for (int kb = 0; kb < 4; kb++) {
                gen_chunk(s + 1, kb);
                mma_kb(s, kb);
            }
        } else {
#pragma unroll
            for (int kb = 0; kb < 4; kb++) mma_kb(s, kb);
        }
        __syncthreads();
    }

    // ---- write partial tile ----
    float* pp = g_part + ((size_t)(ks * BN + b) * MPAD) * KK + n0;
    int tig = lane & 3;
#pragma unroll
    for (int mf = 0; mf < 3; mf++) {
        int r0 = warpM * 48 + mf * 16 + g;
#pragma unroll
        for (int nf = 0; nf < 4; nf++) {
            int cc = nbase + nf * 8 + tig * 2;
            if (r0 < DD)
                *(float2*)(pp + (size_t)r0 * KK + cc)       = make_float2(acc[mf][nf][0], acc[mf][nf][1]);
            if (r0 + 8 < DD)
                *(float2*)(pp + (size_t)(r0 + 8) * KK + cc) = make_float2(acc[mf][nf][2], acc[mf][nf][3]);
        }
    }

    // ---- last-arriving slice CTA reduces this (b, ntile) tile ----
    __shared__ int s_last;
    __threadfence();                          // release partial writes
    __syncthreads();                          // all threads' STGs issued before tid 0 arrives
    if (tid == 0) {
        int old = atomicAdd(&g_sync[b * 8 + blockIdx.x], 1);
        s_last = (old == KSPLIT - 1) ? 1 : 0;
    }
    __syncthreads();
    if (s_last) {
        __threadfence();                      // acquire other slices' writes
        const size_t slice = (size_t)BN * MPAD * KK;
        float* yb = y + (size_t)b * DD * KK + n0;
        const float* p0b = g_part + ((size_t)b * MPAD) * KK + n0;
        for (int i = tid; i < DD * 64; i += 512) {    // 64 float4 per row
            int d = i >> 6, cq = (i & 63) * 4;
            const float* pr = p0b + (size_t)d * KK + cq;
            float4 v0 = *(const float4*)(pr);
            float4 v1 = *(const float4*)(pr + slice);
            float4 v2 = *(const float4*)(pr + 2 * slice);
            float4 v3 = *(const float4*)(pr + 3 * slice);
            *(float4*)(yb + (size_t)d * KK + cq) =
                make_float4(v0.x + v1.x + v2.x + v3.x,
                            v0.y + v1.y + v2.y + v3.y,
                            v0.z + v1.z + v2.z + v3.z,
                            v0.w + v1.w + v2.w + v3.w);
        }
    }
}

// ---------------- launch ----------------
extern "C" void kernel_launch(void* const* d_in, const int* in_sizes, int n_in,
                              void* d_out, int out_size) {
    const float* x   = (const float*)d_in[0];  // (B, D, K)
    const float* pi  = (const float*)d_in[1];  // (B, 1, K)
    const float* mu  = (const float*)d_in[2];  // (B, ND, K)
    const float* sig = (const float*)d_in[3];  // (B, ND, K)
    float* y = (float*)d_out;                  // (B, D, K)

    cudaFuncSetAttribute(gemm_fused, cudaFuncAttributeMaxDynamicSharedMemorySize, DYN_SMEM);

    prep_kernel<<<dim3(128, BN), 256>>>(x, pi, mu, sig);
    rowsum_kernel<<<dim3(KK / 16, BN), 256>>>();
    gemm_fused<<<dim3(KK / NTILE, KSPLIT, BN), 512, DYN_SMEM>>>(y);
}